// round 3
// baseline (speedup 1.0000x reference)
#include <cuda_runtime.h>
#include <cuda_bf16.h>
#include <cstdint>
#include <cstddef>

#define N_EDGES 640000
#define N_NODES 40000
#define DIM 128
#define NRAD 16

// Scratch (allocation-free rule: __device__ globals)
__device__ float g_nodes0[(size_t)N_NODES * DIM];
__device__ float g_nodes1[(size_t)N_NODES * DIM];
__device__ int   g_idx_is64;

// ---------------------------------------------------------------------------
// Detect whether idx_i buffer is int64 or int32.
// If int64 (little-endian, node ids < 40000 < 2^32), every odd 32-bit word
// is 0. If int32, 32 consecutive odd-position zeros is (prob ~0) impossible
// for random idx in [0, 40000).
// ---------------------------------------------------------------------------
__global__ void detect_idx_kernel(const int* __restrict__ idx32) {
    if (blockIdx.x == 0 && threadIdx.x == 0) {
        int f = 1;
        #pragma unroll
        for (int i = 1; i < 64; i += 2)
            if (idx32[i] != 0) f = 0;
        g_idx_is64 = f;
    }
}

// ---------------------------------------------------------------------------
// Edge phase: h[e,d] = (rbf[e,:] . W_rbf[d,:]) * x[e,d], scatter-add to nodes.
// blockDim = 128 (one thread per dim). 16 edges per shared batch.
// ---------------------------------------------------------------------------
#define EDGE_BATCH 16

__global__ void edge_kernel(const float* __restrict__ x,
                            const float* __restrict__ rbf,
                            const void*  __restrict__ idx,
                            const float* __restrict__ Wrbf)
{
    const int d = threadIdx.x;  // 0..127
    float w[NRAD];
    #pragma unroll
    for (int k = 0; k < NRAD; k++) w[k] = Wrbf[d * NRAD + k];

    __shared__ float s_rbf[EDGE_BATCH][NRAD];
    __shared__ int   s_idx[EDGE_BATCH];

    const int is64 = g_idx_is64;
    const long long* idx64 = (const long long*)idx;
    const int*       idx32 = (const int*)idx;

    const int nbatch = N_EDGES / EDGE_BATCH;
    for (int b = blockIdx.x; b < nbatch; b += gridDim.x) {
        const int e0 = b * EDGE_BATCH;
        // 128 threads load 16*16=256 rbf values coalesced (2 per thread)
        #pragma unroll
        for (int i = 0; i < (EDGE_BATCH * NRAD) / 128; i++) {
            const int li = i * 128 + d;
            s_rbf[li >> 4][li & 15] = rbf[(size_t)e0 * NRAD + li];
        }
        if (d < EDGE_BATCH)
            s_idx[d] = is64 ? (int)idx64[e0 + d] : idx32[e0 + d];
        __syncthreads();

        #pragma unroll
        for (int e = 0; e < EDGE_BATCH; e++) {
            float proj = 0.f;
            #pragma unroll
            for (int k = 0; k < NRAD; k++)
                proj = fmaf(w[k], s_rbf[e][k], proj);
            const float v = proj * x[(size_t)(e0 + e) * DIM + d];
            atomicAdd(&g_nodes0[(size_t)s_idx[e] * DIM + d], v);
        }
        __syncthreads();
    }
}

// ---------------------------------------------------------------------------
// Dense layer: B[i,j] = silu(sum_k A[i,k] * W[j,k] + bias[j])
// Block: 64 rows x 128 cols. 256 threads, 8x4 register tile each.
// Dynamic smem: Ws[128][132] (transposed W) + As[64][129].
// ---------------------------------------------------------------------------
#define L_TILE_M 64
#define L_WS_STRIDE 132
#define L_AS_STRIDE 129
#define L_SMEM_BYTES ((128 * L_WS_STRIDE + L_TILE_M * L_AS_STRIDE) * 4)

__global__ void layer_kernel(const float* __restrict__ A,
                             float* __restrict__ B,
                             const float* __restrict__ W,
                             const float* __restrict__ bias)
{
    extern __shared__ float smem[];
    float* Ws = smem;                          // [128][132] : Ws[k][j] = W[j][k]
    float* As = smem + 128 * L_WS_STRIDE;      // [64][129]

    const int t = threadIdx.x;  // 0..255

    // Load W transposed (coalesced global reads)
    for (int i = t; i < 128 * 128; i += 256) {
        const int j = i >> 7, k = i & 127;
        Ws[k * L_WS_STRIDE + j] = W[i];
    }
    // Load A tile (coalesced)
    const size_t i0 = (size_t)blockIdx.x * L_TILE_M;
    for (int i = t; i < L_TILE_M * 128; i += 256) {
        const int r = i >> 7, k = i & 127;
        As[r * L_AS_STRIDE + k] = A[(i0 + r) * DIM + k];
    }
    __syncthreads();

    const int c0 = (t & 31) * 4;   // output col base (float4 aligned)
    const int r0 = (t >> 5) * 8;   // output row base

    float acc[8][4];
    #pragma unroll
    for (int i = 0; i < 8; i++)
        #pragma unroll
        for (int j = 0; j < 4; j++) acc[i][j] = 0.f;

    #pragma unroll 4
    for (int k = 0; k < 128; k++) {
        const float4 wv = *(const float4*)&Ws[k * L_WS_STRIDE + c0];
        float a[8];
        #pragma unroll
        for (int i = 0; i < 8; i++) a[i] = As[(r0 + i) * L_AS_STRIDE + k];
        #pragma unroll
        for (int i = 0; i < 8; i++) {
            acc[i][0] = fmaf(a[i], wv.x, acc[i][0]);
            acc[i][1] = fmaf(a[i], wv.y, acc[i][1]);
            acc[i][2] = fmaf(a[i], wv.z, acc[i][2]);
            acc[i][3] = fmaf(a[i], wv.w, acc[i][3]);
        }
    }

    const float4 bv = *(const float4*)&bias[c0];
    #pragma unroll
    for (int i = 0; i < 8; i++) {
        float4 o;
        float v;
        v = acc[i][0] + bv.x; o.x = v / (1.f + __expf(-v));
        v = acc[i][1] + bv.y; o.y = v / (1.f + __expf(-v));
        v = acc[i][2] + bv.z; o.z = v / (1.f + __expf(-v));
        v = acc[i][3] + bv.w; o.w = v / (1.f + __expf(-v));
        *(float4*)&B[(i0 + r0 + i) * DIM + c0] = o;
    }
}

// ---------------------------------------------------------------------------
// Final projection: out[i] = sum_j A[i,j] * Wout[j]   (warp per node)
// ---------------------------------------------------------------------------
__global__ void out_kernel(const float* __restrict__ A,
                           const float* __restrict__ Wout,
                           float* __restrict__ out)
{
    const int node = blockIdx.x * 8 + (threadIdx.x >> 5);
    const int lane = threadIdx.x & 31;
    if (node >= N_NODES) return;
    const float4 w = *(const float4*)&Wout[lane * 4];
    const float4 v = *(const float4*)&A[(size_t)node * DIM + lane * 4];
    float s = v.x * w.x + v.y * w.y + v.z * w.z + v.w * w.w;
    #pragma unroll
    for (int o = 16; o; o >>= 1) s += __shfl_xor_sync(0xffffffffu, s, o);
    if (lane == 0) out[node] = s;
}

// ---------------------------------------------------------------------------
extern "C" void kernel_launch(void* const* d_in, const int* in_sizes, int n_in,
                              void* d_out, int out_size)
{
    const float* x    = (const float*)d_in[0];
    const float* rbf  = (const float*)d_in[1];
    const void*  idx  = d_in[2];
    // num_nodes may or may not be materialized as a 1-element buffer.
    // Two signals: in_sizes[3]==1 (scalar buffer at slot 3), or n_in==12.
    const int wb = ((n_in >= 12) || (in_sizes[3] == 1)) ? 4 : 3;
    const float* Wrbf = (const float*)d_in[wb + 0];
    const float* W1   = (const float*)d_in[wb + 1];
    const float* b1   = (const float*)d_in[wb + 2];
    const float* W2   = (const float*)d_in[wb + 3];
    const float* b2   = (const float*)d_in[wb + 4];
    const float* W3   = (const float*)d_in[wb + 5];
    const float* b3   = (const float*)d_in[wb + 6];
    const float* Wout = (const float*)d_in[wb + 7];
    float* out = (float*)d_out;

    float *n0, *n1;
    cudaGetSymbolAddress((void**)&n0, g_nodes0);
    cudaGetSymbolAddress((void**)&n1, g_nodes1);

    cudaMemsetAsync(n0, 0, (size_t)N_NODES * DIM * sizeof(float));

    detect_idx_kernel<<<1, 1>>>((const int*)idx);

    edge_kernel<<<1184, 128>>>(x, rbf, idx, Wrbf);

    cudaFuncSetAttribute(layer_kernel,
                         cudaFuncAttributeMaxDynamicSharedMemorySize, L_SMEM_BYTES);

    layer_kernel<<<N_NODES / L_TILE_M, 256, L_SMEM_BYTES>>>(n0, n1, W1, b1);
    layer_kernel<<<N_NODES / L_TILE_M, 256, L_SMEM_BYTES>>>(n1, n0, W2, b2);
    layer_kernel<<<N_NODES / L_TILE_M, 256, L_SMEM_BYTES>>>(n0, n1, W3, b3);

    out_kernel<<<(N_NODES + 7) / 8, 256>>>(n1, Wout, out);
}